// round 12
// baseline (speedup 1.0000x reference)
#include <cuda_runtime.h>
#include <cuda_fp16.h>
#include <math.h>

constexpr int Bq   = 4;
constexpr int Nq   = 64;
constexpr int Fq   = 64;
constexpr int FINq = 32;
constexpr int EDIMq= 32;
constexpr int FFq  = Fq * Fq;          // 4096
constexpr int ROWS = Bq * Nq;          // 256 target rows (b,n)
constexpr int NGRP = 4;                // aggregation groups per row

__device__ float  g_H[ROWS * Fq];
__device__ float  g_H2[ROWS * Fq];
__device__ float  g_pagg[NGRP * ROWS * Fq];   // per-group partial aggregates
__device__ int    g_done[ROWS];               // completion counters (self-resetting)
__device__ int    g_cnt[ROWS];
__device__ int    g_midx[ROWS * Nq];
// Interleaved: per slot 2048 half2; entry c (c = ii*64+j, ii<32) holds
// (A[ii][j], A[ii+32][j]).
__device__ __align__(16) __half2 g_Amat[(size_t)ROWS * Nq * (FFq / 2)];

__device__ __forceinline__ float sigm(float x) { return 1.0f / (1.0f + expf(-x)); }
__device__ __forceinline__ __half2 h2(unsigned int u) {
    return *reinterpret_cast<__half2*>(&u);
}
__device__ __forceinline__ unsigned long long pack2(float lo, float hi) {
    unsigned long long r;
    asm("mov.b64 %0, {%1, %2};" : "=l"(r) : "f"(lo), "f"(hi));
    return r;
}
__device__ __forceinline__ void unpack2(unsigned long long v, float& lo, float& hi) {
    asm("mov.b64 {%0, %1}, %2;" : "=f"(lo), "=f"(hi) : "l"(v));
}
__device__ __forceinline__ unsigned long long ffma2(
    unsigned long long a, unsigned long long b, unsigned long long c) {
    unsigned long long d;
    asm("fma.rn.f32x2 %0, %1, %2, %3;" : "=l"(d) : "l"(a), "l"(b), "l"(c));
    return d;
}

// ---------------------------------------------------------------------------
// Kernel 1: edge MLP (ballot compaction + interleaved fp16 out) + embedding.
// Block (rp, by): rows {2rp, 2rp+1} x column pairs (c0+t, c0+t+2048).
// by==0 blocks publish g_cnt / g_midx and compute H0 for their 2 rows.
// ---------------------------------------------------------------------------
__global__ __launch_bounds__(256) void k_edge(
    const float* __restrict__ A, const float* __restrict__ E,
    const float* __restrict__ X,
    const float* __restrict__ W_embed, const float* __restrict__ b_embed,
    const float* __restrict__ W_edge, const float* __restrict__ b_edge)
{
    __shared__ unsigned long long Es2[128 * EDIMq];   // 32KB
    __shared__ int s_m[128];
    __shared__ int s_cnt[2];

    int rp = blockIdx.x, by = blockIdx.y, c0 = by * 256, t = threadIdx.x;

    if (t < 64) {
        int r = t >> 5, lane = t & 31;
        int row = rp * 2 + r;
        const float* Arow = A + (size_t)row * Nq;
        unsigned a0 = (Arow[lane] > 0.5f) ? 1u : 0u;
        unsigned a1 = (Arow[32 + lane] > 0.5f) ? 1u : 0u;
        unsigned m0 = __ballot_sync(0xffffffffu, a0);
        unsigned m1 = __ballot_sync(0xffffffffu, a1);
        unsigned lm = (lane == 0) ? 0u : (0xffffffffu >> (32 - lane));
        int n0 = __popc(m0);
        if (a0) { int p = __popc(m0 & lm); s_m[r * 64 + p] = lane;
                  if (by == 0) g_midx[row * Nq + p] = lane; }
        if (a1) { int p = n0 + __popc(m1 & lm); s_m[r * 64 + p] = 32 + lane;
                  if (by == 0) g_midx[row * Nq + p] = 32 + lane; }
        if (lane == 0) { int c = n0 + __popc(m1); s_cnt[r] = c;
                         if (by == 0) g_cnt[row] = c; }
    }

    // embedding for this block's 2 rows (only by==0 publishes)
    if (by == 0 && t >= 128) {
        int r = (t - 128) >> 6, f = t & 63;
        int row = rp * 2 + r;
        float acc = b_embed[f];
#pragma unroll
        for (int k = 0; k < FINq; k++)
            acc += X[(size_t)row * FINq + k] * W_embed[k * Fq + f];
        g_H[(size_t)row * Fq + f] = fmaxf(acc, 0.0f);
    }
    __syncthreads();
    int cnt0 = s_cnt[0], ne = cnt0 + s_cnt[1];

    for (int i = t; i < ne * EDIMq; i += 256) {
        int kk = i >> 5, e = i & 31;
        int p  = (kk >= cnt0) ? 1 : 0;
        int kl = kk - (p ? cnt0 : 0);
        int row = rp * 2 + p;
        int m  = s_m[p * 64 + kl];
        float v = E[((size_t)row * Nq + m) * EDIMq + e];
        Es2[kk * EDIMq + e] = pack2(v, v);
    }
    __syncthreads();

    int c_a = c0 + t, c_b = c_a + 2048;
    unsigned long long w01[EDIMq];
#pragma unroll
    for (int e = 0; e < EDIMq; e++)
        w01[e] = pack2(W_edge[(size_t)e * FFq + c_a], W_edge[(size_t)e * FFq + c_b]);
    unsigned long long bias01 = pack2(b_edge[c_a], b_edge[c_b]);

    auto emit = [&](int kk, unsigned long long acc) {
        float a0, a1;
        unpack2(acc, a0, a1);
        int p  = (kk >= cnt0) ? 1 : 0;
        int kl = kk - (p ? cnt0 : 0);
        size_t slot = (size_t)(rp * 2 + p) * Nq + kl;
        g_Amat[slot * (FFq / 2) + c_a] =
            __floats2half2_rn(fmaxf(a0, 0.0f), fmaxf(a1, 0.0f));
    };

    int kk = 0;
    for (; kk + 2 <= ne; kk += 2) {
        unsigned long long acc0 = bias01, acc1 = bias01;
#pragma unroll
        for (int e = 0; e < EDIMq; e++) {
            acc0 = ffma2(Es2[kk * EDIMq + e],       w01[e], acc0);
            acc1 = ffma2(Es2[(kk + 1) * EDIMq + e], w01[e], acc1);
        }
        emit(kk, acc0);
        emit(kk + 1, acc1);
    }
    if (kk < ne) {
        unsigned long long acc0 = bias01;
#pragma unroll
        for (int e = 0; e < EDIMq; e++)
            acc0 = ffma2(Es2[kk * EDIMq + e], w01[e], acc0);
        emit(kk, acc0);
    }
}

// ---------------------------------------------------------------------------
// Kernel 2: one round = partial aggregation (grid ROWS*NGRP, 256 thr) with the
// GRU run INLINE by the last-arriving block per row (threadfence-reduction
// pattern; counter self-resets -> graph-replay safe).
// Thread map: ii = t>>3 (feature pair ii/ii+32), jq = t&7 (8 j's).
// Block (row,g) handles edges e = g, g+4, g+8, ... (strided, balanced).
// ---------------------------------------------------------------------------
__global__ __launch_bounds__(256) void k_round(
    const float* __restrict__ Hin, float* __restrict__ Hout,
    const float* __restrict__ gk, const float* __restrict__ grk,
    const float* __restrict__ gb, const float* __restrict__ grb)
{
    int bid = blockIdx.x;
    int row = bid >> 2;
    int g   = bid & 3;
    int b   = row >> 6;
    int t = threadIdx.x;
    int ii = t >> 3, jq = t & 7;

    __shared__ __half2 hs2[16][Fq];    // up to 16 edges' dup-h states (4KB)
    __shared__ int amLast;
    __shared__ float xold[Fq], aggv[Fq], h1[Fq];
    __shared__ float xg1[3 * Fq], xg2[3 * Fq], hg2[3 * Fq];

    int cnt = g_cnt[row];
    int ne = (cnt > g) ? ((cnt - g + NGRP - 1) >> 2) : 0;

    for (int idx = t; idx < ne * Fq; idx += 256) {
        int e = idx >> 6, j = idx & 63;
        int m = g_midx[row * Nq + g + 4 * e];
        hs2[e][j] = __float2half2_rn(Hin[((size_t)b * Nq + m) * Fq + j]);
    }
    __syncthreads();

    // ---- aggregation: per edge 2 uint4 A (32B) + 2 uint4 h, 8 HFMA2 ----
    const uint4* Ab = reinterpret_cast<const uint4*>(g_Amat);
    float flo = 0.0f, fhi = 0.0f;
    for (int e = 0; e < ne; e++) {
        size_t slot = (size_t)row * Nq + g + 4 * e;
        const uint4* ap = Ab + slot * 512 + ii * 16 + jq * 2;
        uint4 a0 = ap[0];
        uint4 a1 = ap[1];
        const uint4* hp = reinterpret_cast<const uint4*>(&hs2[e][jq * 8]);
        uint4 h0 = hp[0];
        uint4 h1v = hp[1];
        __half2 cA = __hmul2(h2(a0.x), h2(h0.x));
        cA = __hfma2(h2(a0.y), h2(h0.y), cA);
        cA = __hfma2(h2(a0.z), h2(h0.z), cA);
        cA = __hfma2(h2(a0.w), h2(h0.w), cA);
        __half2 cB = __hmul2(h2(a1.x), h2(h1v.x));
        cB = __hfma2(h2(a1.y), h2(h1v.y), cB);
        cB = __hfma2(h2(a1.z), h2(h1v.z), cB);
        cB = __hfma2(h2(a1.w), h2(h1v.w), cB);
        float2 f = __half22float2(__hadd2(cA, cB));
        flo += f.x;
        fhi += f.y;
    }
    flo += __shfl_xor_sync(0xffffffffu, flo, 1);
    flo += __shfl_xor_sync(0xffffffffu, flo, 2);
    flo += __shfl_xor_sync(0xffffffffu, flo, 4);
    fhi += __shfl_xor_sync(0xffffffffu, fhi, 1);
    fhi += __shfl_xor_sync(0xffffffffu, fhi, 2);
    fhi += __shfl_xor_sync(0xffffffffu, fhi, 4);
    if (jq == 0) {
        g_pagg[((size_t)g * ROWS + row) * Fq + ii]      = flo;
        g_pagg[((size_t)g * ROWS + row) * Fq + ii + 32] = fhi;
    }

    // ---- completion: last block for this row runs the GRU ----
    __threadfence();
    __syncthreads();
    if (t == 0) {
        int old = atomicAdd(&g_done[row], 1);
        amLast = (old == NGRP - 1);
        if (amLast) {
            g_done[row] = 0;      // reset for next round / next replay
            __threadfence();
        }
    }
    __syncthreads();
    if (!amLast) return;

    if (t < Fq) {
        aggv[t] = __ldcg(&g_pagg[((size_t)0 * ROWS + row) * Fq + t])
                + __ldcg(&g_pagg[((size_t)1 * ROWS + row) * Fq + t])
                + __ldcg(&g_pagg[((size_t)2 * ROWS + row) * Fq + t])
                + __ldcg(&g_pagg[((size_t)3 * ROWS + row) * Fq + t]);
        xold[t] = Hin[(size_t)row * Fq + t];
    }
    __syncthreads();

    // one pass over gk computes both steps' input gates
    if (t < 192) {
        float a1 = gb[t], a2 = gb[t];
#pragma unroll 8
        for (int j = 0; j < Fq; j++) {
            float w = gk[j * 192 + t];
            a1 += xold[j] * w;
            a2 += aggv[j] * w;
        }
        xg1[t] = a1;
        xg2[t] = a2;
    }
    __syncthreads();
    if (t < Fq) {
        float z = sigm(xg1[t] + grb[t]);
        float r = sigm(xg1[Fq + t] + grb[Fq + t]);
        float cand = tanhf(xg1[2 * Fq + t] + r * grb[2 * Fq + t]);
        h1[t] = (1.0f - z) * cand;
    }
    __syncthreads();
    if (t < 192) {
        float hh = grb[t];
#pragma unroll 8
        for (int j = 0; j < Fq; j++) hh += h1[j] * grk[j * 192 + t];
        hg2[t] = hh;
    }
    __syncthreads();
    if (t < Fq) {
        float z = sigm(xg2[t] + hg2[t]);
        float r = sigm(xg2[Fq + t] + hg2[Fq + t]);
        float cand = tanhf(xg2[2 * Fq + t] + r * hg2[2 * Fq + t]);
        Hout[(size_t)row * Fq + t] = z * h1[t] + (1.0f - z) * cand;
    }
}

// ---------------------------------------------------------------------------
extern "C" void kernel_launch(void* const* d_in, const int* in_sizes, int n_in,
                              void* d_out, int out_size)
{
    const float* X       = (const float*)d_in[0];
    const float* A       = (const float*)d_in[1];
    const float* E       = (const float*)d_in[2];
    const float* W_embed = (const float*)d_in[3];
    const float* b_embed = (const float*)d_in[4];
    const float* W_edge  = (const float*)d_in[5];
    const float* b_edge  = (const float*)d_in[6];
    const float* gk      = (const float*)d_in[7];
    const float* grk     = (const float*)d_in[8];
    const float* gb      = (const float*)d_in[9];
    const float* grb     = (const float*)d_in[10];
    float* out = (float*)d_out;

    float *hbuf = nullptr, *h2buf = nullptr;
    cudaGetSymbolAddress((void**)&hbuf, g_H);
    cudaGetSymbolAddress((void**)&h2buf, g_H2);

    k_edge<<<dim3(ROWS / 2, 8), 256>>>(A, E, X, W_embed, b_embed,
                                       W_edge, b_edge);
    k_round<<<ROWS * NGRP, 256>>>(hbuf,  h2buf, gk, grk, gb, grb);
    k_round<<<ROWS * NGRP, 256>>>(h2buf, hbuf,  gk, grk, gb, grb);
    k_round<<<ROWS * NGRP, 256>>>(hbuf,  out,   gk, grk, gb, grb);
}

// round 13
// speedup vs baseline: 1.1177x; 1.1177x over previous
#include <cuda_runtime.h>
#include <cuda_fp16.h>
#include <math.h>

constexpr int Bq   = 4;
constexpr int Nq   = 64;
constexpr int Fq   = 64;
constexpr int FINq = 32;
constexpr int EDIMq= 32;
constexpr int FFq  = Fq * Fq;          // 4096
constexpr int ROWS = Bq * Nq;          // 256 target rows (b,n)

constexpr int NSTAGE = 8;              // ring stages (1 slot = 8KB each)

__device__ float  g_H[ROWS * Fq];
__device__ float  g_H2[ROWS * Fq];
__device__ int    g_cnt[ROWS];
__device__ int    g_midx[ROWS * Nq];
// Interleaved: per slot 2048 half2; entry c (c = ii*64+j, ii<32) holds
// (A[ii][j], A[ii+32][j]).
__device__ __align__(16) __half2 g_Amat[(size_t)ROWS * Nq * (FFq / 2)];

__device__ __forceinline__ float sigm(float x) { return 1.0f / (1.0f + expf(-x)); }
__device__ __forceinline__ __half2 h2(unsigned int u) {
    return *reinterpret_cast<__half2*>(&u);
}
__device__ __forceinline__ unsigned long long pack2(float lo, float hi) {
    unsigned long long r;
    asm("mov.b64 %0, {%1, %2};" : "=l"(r) : "f"(lo), "f"(hi));
    return r;
}
__device__ __forceinline__ void unpack2(unsigned long long v, float& lo, float& hi) {
    asm("mov.b64 {%0, %1}, %2;" : "=f"(lo), "=f"(hi) : "l"(v));
}
__device__ __forceinline__ unsigned long long ffma2(
    unsigned long long a, unsigned long long b, unsigned long long c) {
    unsigned long long d;
    asm("fma.rn.f32x2 %0, %1, %2, %3;" : "=l"(d) : "l"(a), "l"(b), "l"(c));
    return d;
}
__device__ __forceinline__ void cp_async16(void* smem_ptr, const void* gptr) {
    unsigned sa = (unsigned)__cvta_generic_to_shared(smem_ptr);
    asm volatile("cp.async.cg.shared.global [%0], [%1], 16;" :: "r"(sa), "l"(gptr));
}
__device__ __forceinline__ void cp_commit() {
    asm volatile("cp.async.commit_group;");
}
template<int N> __device__ __forceinline__ void cp_wait() {
    asm volatile("cp.async.wait_group %0;" :: "n"(N));
}

// ---------------------------------------------------------------------------
// Kernel 1: edge MLP + embedding + compaction (R12-proven fused form).
// Block (rp, by): rows {2rp, 2rp+1} x column pairs (c0+t, c0+t+2048).
// ---------------------------------------------------------------------------
__global__ __launch_bounds__(256) void k_edge(
    const float* __restrict__ A, const float* __restrict__ E,
    const float* __restrict__ X,
    const float* __restrict__ W_embed, const float* __restrict__ b_embed,
    const float* __restrict__ W_edge, const float* __restrict__ b_edge)
{
    __shared__ unsigned long long Es2[128 * EDIMq];   // 32KB
    __shared__ int s_m[128];
    __shared__ int s_cnt[2];

    int rp = blockIdx.x, by = blockIdx.y, c0 = by * 256, t = threadIdx.x;

    if (t < 64) {
        int r = t >> 5, lane = t & 31;
        int row = rp * 2 + r;
        const float* Arow = A + (size_t)row * Nq;
        unsigned a0 = (Arow[lane] > 0.5f) ? 1u : 0u;
        unsigned a1 = (Arow[32 + lane] > 0.5f) ? 1u : 0u;
        unsigned m0 = __ballot_sync(0xffffffffu, a0);
        unsigned m1 = __ballot_sync(0xffffffffu, a1);
        unsigned lm = (lane == 0) ? 0u : (0xffffffffu >> (32 - lane));
        int n0 = __popc(m0);
        if (a0) { int p = __popc(m0 & lm); s_m[r * 64 + p] = lane;
                  if (by == 0) g_midx[row * Nq + p] = lane; }
        if (a1) { int p = n0 + __popc(m1 & lm); s_m[r * 64 + p] = 32 + lane;
                  if (by == 0) g_midx[row * Nq + p] = 32 + lane; }
        if (lane == 0) { int c = n0 + __popc(m1); s_cnt[r] = c;
                         if (by == 0) g_cnt[row] = c; }
    }

    if (by == 0 && t >= 128) {
        int r = (t - 128) >> 6, f = t & 63;
        int row = rp * 2 + r;
        float acc = b_embed[f];
#pragma unroll
        for (int k = 0; k < FINq; k++)
            acc += X[(size_t)row * FINq + k] * W_embed[k * Fq + f];
        g_H[(size_t)row * Fq + f] = fmaxf(acc, 0.0f);
    }
    __syncthreads();
    int cnt0 = s_cnt[0], ne = cnt0 + s_cnt[1];

    for (int i = t; i < ne * EDIMq; i += 256) {
        int kk = i >> 5, e = i & 31;
        int p  = (kk >= cnt0) ? 1 : 0;
        int kl = kk - (p ? cnt0 : 0);
        int row = rp * 2 + p;
        int m  = s_m[p * 64 + kl];
        float v = E[((size_t)row * Nq + m) * EDIMq + e];
        Es2[kk * EDIMq + e] = pack2(v, v);
    }
    __syncthreads();

    int c_a = c0 + t, c_b = c_a + 2048;
    unsigned long long w01[EDIMq];
#pragma unroll
    for (int e = 0; e < EDIMq; e++)
        w01[e] = pack2(W_edge[(size_t)e * FFq + c_a], W_edge[(size_t)e * FFq + c_b]);
    unsigned long long bias01 = pack2(b_edge[c_a], b_edge[c_b]);

    auto emit = [&](int kk, unsigned long long acc) {
        float a0, a1;
        unpack2(acc, a0, a1);
        int p  = (kk >= cnt0) ? 1 : 0;
        int kl = kk - (p ? cnt0 : 0);
        size_t slot = (size_t)(rp * 2 + p) * Nq + kl;
        g_Amat[slot * (FFq / 2) + c_a] =
            __floats2half2_rn(fmaxf(a0, 0.0f), fmaxf(a1, 0.0f));
    };

    int kk = 0;
    for (; kk + 2 <= ne; kk += 2) {
        unsigned long long acc0 = bias01, acc1 = bias01;
#pragma unroll
        for (int e = 0; e < EDIMq; e++) {
            acc0 = ffma2(Es2[kk * EDIMq + e],       w01[e], acc0);
            acc1 = ffma2(Es2[(kk + 1) * EDIMq + e], w01[e], acc1);
        }
        emit(kk, acc0);
        emit(kk + 1, acc1);
    }
    if (kk < ne) {
        unsigned long long acc0 = bias01;
#pragma unroll
        for (int e = 0; e < EDIMq; e++)
            acc0 = ffma2(Es2[kk * EDIMq + e], w01[e], acc0);
        emit(kk, acc0);
    }
}

// ---------------------------------------------------------------------------
// Kernel 2: one round, BARRIER-FREE streaming. 256 blocks x 512 threads.
// Chunk = 1 slot (8KB) = 512 uint4. Thread t cp.asyncs AND consumes uint4 #t
// (c-values [4t,4t+4) -> ii = t>>4, j = (t&15)*4). Per-thread wait_group is
// the only ordering in the loop -- no __syncthreads until the reduce.
// ---------------------------------------------------------------------------
constexpr int RING_OFF = 0;                          // NSTAGE*8192 = 65536
constexpr int HS_OFF   = NSTAGE * 8192;              // 64*64 half2 = 16384
constexpr int FLT_OFF  = HS_OFF + Nq * Fq * 4;       // floats
constexpr int KSM_TOTAL= FLT_OFF + (64 * 3 + 192 * 3) * 4;   // +3072 -> 84992

__global__ __launch_bounds__(512) void k_round(
    const float* __restrict__ Hin, float* __restrict__ Hout,
    const float* __restrict__ gk, const float* __restrict__ grk,
    const float* __restrict__ gb, const float* __restrict__ grb)
{
    extern __shared__ __align__(16) char smem[];
    char*    ring = smem + RING_OFF;
    __half2* hs2  = reinterpret_cast<__half2*>(smem + HS_OFF);
    float*   fl   = reinterpret_cast<float*>(smem + FLT_OFF);
    float* xold = fl;            // 64
    float* aggv = fl + 64;       // 64
    float* h1   = fl + 128;      // 64
    float* xg1  = fl + 192;      // 192
    float* xg2  = fl + 384;      // 192
    float* hg2  = fl + 576;      // 192

    int row = blockIdx.x;
    int b = row >> 6;
    int t = threadIdx.x;
    int q = t & 15;              // j-chunk: j = q*4..q*4+3

    int cnt = g_cnt[row];
    const char* Asrc = reinterpret_cast<const char*>(g_Amat)
                     + (size_t)row * Nq * 8192;

    // prologue: issue NSTAGE-1 slots (one commit per slot, even if empty)
#pragma unroll
    for (int s = 0; s < NSTAGE - 1; s++) {
        if (s < cnt)
            cp_async16(ring + (s & (NSTAGE - 1)) * 8192 + t * 16,
                       Asrc + (size_t)s * 8192 + t * 16);
        cp_commit();
    }

    // stage source states (dup-half2) + xold while copies fly
    for (int idx = t; idx < cnt * Fq; idx += 512) {
        int e = idx >> 6, j = idx & 63;
        int m = g_midx[row * Nq + e];
        hs2[e * Fq + j] = __float2half2_rn(Hin[((size_t)b * Nq + m) * Fq + j]);
    }
    if (t >= 448) xold[t - 448] = Hin[(size_t)row * Fq + (t - 448)];
    __syncthreads();             // hs2/xold visible; loop below is barrier-free

    float flo = 0.0f, fhi = 0.0f;
    for (int c = 0; c < cnt; c++) {
        cp_wait<NSTAGE - 2>();   // per-thread: my 16B of chunk c has landed
        uint4 a  = *reinterpret_cast<const uint4*>(
                       ring + (c & (NSTAGE - 1)) * 8192 + t * 16);
        uint4 hv = *reinterpret_cast<const uint4*>(hs2 + c * Fq + q * 4);
        __half2 c2 = __hmul2(h2(a.x), h2(hv.x));
        c2 = __hfma2(h2(a.y), h2(hv.y), c2);
        c2 = __hfma2(h2(a.z), h2(hv.z), c2);
        c2 = __hfma2(h2(a.w), h2(hv.w), c2);
        float2 f = __half22float2(c2);
        flo += f.x;
        fhi += f.y;
        int nx = c + NSTAGE - 1;
        if (nx < cnt)            // ring slot (c-1)&7: already consumed by me
            cp_async16(ring + (nx & (NSTAGE - 1)) * 8192 + t * 16,
                       Asrc + (size_t)nx * 8192 + t * 16);
        cp_commit();
    }
    cp_wait<0>();

    // reduce over the 16 j-lanes
    flo += __shfl_xor_sync(0xffffffffu, flo, 1);
    flo += __shfl_xor_sync(0xffffffffu, flo, 2);
    flo += __shfl_xor_sync(0xffffffffu, flo, 4);
    flo += __shfl_xor_sync(0xffffffffu, flo, 8);
    fhi += __shfl_xor_sync(0xffffffffu, fhi, 1);
    fhi += __shfl_xor_sync(0xffffffffu, fhi, 2);
    fhi += __shfl_xor_sync(0xffffffffu, fhi, 4);
    fhi += __shfl_xor_sync(0xffffffffu, fhi, 8);
    if (q == 0) {
        int ii = t >> 4;
        aggv[ii]      = flo;
        aggv[ii + 32] = fhi;
    }
    __syncthreads();

    // ---- GRU: one pass over gk computes both steps' input gates ----
    if (t < 192) {
        float a1 = gb[t], a2 = gb[t];
#pragma unroll 8
        for (int j = 0; j < Fq; j++) {
            float w = gk[j * 192 + t];
            a1 += xold[j] * w;
            a2 += aggv[j] * w;
        }
        xg1[t] = a1;
        xg2[t] = a2;
    }
    __syncthreads();
    if (t < Fq) {
        float z = sigm(xg1[t] + grb[t]);
        float rr = sigm(xg1[Fq + t] + grb[Fq + t]);
        float cand = tanhf(xg1[2 * Fq + t] + rr * grb[2 * Fq + t]);
        h1[t] = (1.0f - z) * cand;
    }
    __syncthreads();
    if (t < 192) {
        float hh = grb[t];
#pragma unroll 8
        for (int j = 0; j < Fq; j++) hh += h1[j] * grk[j * 192 + t];
        hg2[t] = hh;
    }
    __syncthreads();
    if (t < Fq) {
        float z = sigm(xg2[t] + hg2[t]);
        float rr = sigm(xg2[Fq + t] + hg2[Fq + t]);
        float cand = tanhf(xg2[2 * Fq + t] + rr * hg2[2 * Fq + t]);
        Hout[(size_t)row * Fq + t] = z * h1[t] + (1.0f - z) * cand;
    }
}

// ---------------------------------------------------------------------------
extern "C" void kernel_launch(void* const* d_in, const int* in_sizes, int n_in,
                              void* d_out, int out_size)
{
    const float* X       = (const float*)d_in[0];
    const float* A       = (const float*)d_in[1];
    const float* E       = (const float*)d_in[2];
    const float* W_embed = (const float*)d_in[3];
    const float* b_embed = (const float*)d_in[4];
    const float* W_edge  = (const float*)d_in[5];
    const float* b_edge  = (const float*)d_in[6];
    const float* gk      = (const float*)d_in[7];
    const float* grk     = (const float*)d_in[8];
    const float* gb      = (const float*)d_in[9];
    const float* grb     = (const float*)d_in[10];
    float* out = (float*)d_out;

    float *hbuf = nullptr, *h2buf = nullptr;
    cudaGetSymbolAddress((void**)&hbuf, g_H);
    cudaGetSymbolAddress((void**)&h2buf, g_H2);

    static bool attr_set = false;
    if (!attr_set) {
        cudaFuncSetAttribute(k_round, cudaFuncAttributeMaxDynamicSharedMemorySize,
                             KSM_TOTAL);
        attr_set = true;
    }

    k_edge<<<dim3(ROWS / 2, 8), 256>>>(A, E, X, W_embed, b_embed,
                                       W_edge, b_edge);
    k_round<<<ROWS, 512, KSM_TOTAL>>>(hbuf,  h2buf, gk, grk, gb, grb);
    k_round<<<ROWS, 512, KSM_TOTAL>>>(h2buf, hbuf,  gk, grk, gb, grb);
    k_round<<<ROWS, 512, KSM_TOTAL>>>(hbuf,  out,   gk, grk, gb, grb);
}

// round 14
// speedup vs baseline: 1.1723x; 1.0488x over previous
#include <cuda_runtime.h>
#include <cuda_fp16.h>
#include <math.h>

constexpr int Bq   = 4;
constexpr int Nq   = 64;
constexpr int Fq   = 64;
constexpr int FINq = 32;
constexpr int EDIMq= 32;
constexpr int FFq  = Fq * Fq;          // 4096
constexpr int ROWS = Bq * Nq;          // 256 target rows (b,n)

constexpr int CHUNK_E = 4;             // edges per bulk chunk (32KB)
constexpr int NRING   = 2;             // double buffer

__device__ float  g_H[ROWS * Fq];
__device__ float  g_H2[ROWS * Fq];
__device__ int    g_cnt[ROWS];
__device__ int    g_midx[ROWS * Nq];
// Interleaved: per slot 2048 half2; entry c (c = ii*64+j, ii<32) holds
// (A[ii][j], A[ii+32][j]).
__device__ __align__(16) __half2 g_Amat[(size_t)ROWS * Nq * (FFq / 2)];

__device__ __forceinline__ float sigm(float x) { return 1.0f / (1.0f + expf(-x)); }
__device__ __forceinline__ __half2 h2(unsigned int u) {
    return *reinterpret_cast<__half2*>(&u);
}
__device__ __forceinline__ unsigned long long pack2(float lo, float hi) {
    unsigned long long r;
    asm("mov.b64 %0, {%1, %2};" : "=l"(r) : "f"(lo), "f"(hi));
    return r;
}
__device__ __forceinline__ void unpack2(unsigned long long v, float& lo, float& hi) {
    asm("mov.b64 {%0, %1}, %2;" : "=f"(lo), "=f"(hi) : "l"(v));
}
__device__ __forceinline__ unsigned long long ffma2(
    unsigned long long a, unsigned long long b, unsigned long long c) {
    unsigned long long d;
    asm("fma.rn.f32x2 %0, %1, %2, %3;" : "=l"(d) : "l"(a), "l"(b), "l"(c));
    return d;
}
__device__ __forceinline__ unsigned smem_u32(const void* p) {
    return (unsigned)__cvta_generic_to_shared(p);
}
__device__ __forceinline__ void mbar_init(unsigned mbar, unsigned count) {
    asm volatile("mbarrier.init.shared.b64 [%0], %1;" :: "r"(mbar), "r"(count) : "memory");
}
__device__ __forceinline__ void mbar_expect_tx(unsigned mbar, unsigned bytes) {
    asm volatile("mbarrier.arrive.expect_tx.shared.b64 _, [%0], %1;"
                 :: "r"(mbar), "r"(bytes) : "memory");
}
__device__ __forceinline__ void mbar_wait(unsigned mbar, unsigned phase) {
    unsigned done;
    asm volatile(
        "{\n\t.reg .pred p;\n\t"
        "mbarrier.try_wait.parity.acquire.cta.shared::cta.b64 p, [%1], %2;\n\t"
        "selp.b32 %0, 1, 0, p;\n\t}"
        : "=r"(done) : "r"(mbar), "r"(phase) : "memory");
    if (!done) {
        asm volatile(
            "{\n\t.reg .pred P1;\n\t"
            "WL_%=:\n\t"
            "mbarrier.try_wait.parity.acquire.cta.shared::cta.b64 P1, [%0], %1, 0x989680;\n\t"
            "@P1 bra.uni WD_%=;\n\t"
            "bra.uni WL_%=;\n\t"
            "WD_%=:\n\t}"
            :: "r"(mbar), "r"(phase) : "memory");
    }
}
__device__ __forceinline__ void bulk_ld(unsigned dst_smem, const void* src,
                                        unsigned bytes, unsigned mbar) {
    asm volatile(
        "cp.async.bulk.shared::cta.global.mbarrier::complete_tx::bytes [%0], [%1], %2, [%3];"
        :: "r"(dst_smem), "l"(src), "r"(bytes), "r"(mbar) : "memory");
}

// ---------------------------------------------------------------------------
// Kernel 1: edge MLP + embedding + compaction (R13-proven fused form).
// ---------------------------------------------------------------------------
__global__ __launch_bounds__(256) void k_edge(
    const float* __restrict__ A, const float* __restrict__ E,
    const float* __restrict__ X,
    const float* __restrict__ W_embed, const float* __restrict__ b_embed,
    const float* __restrict__ W_edge, const float* __restrict__ b_edge)
{
    __shared__ unsigned long long Es2[128 * EDIMq];   // 32KB
    __shared__ int s_m[128];
    __shared__ int s_cnt[2];

    int rp = blockIdx.x, by = blockIdx.y, c0 = by * 256, t = threadIdx.x;

    if (t < 64) {
        int r = t >> 5, lane = t & 31;
        int row = rp * 2 + r;
        const float* Arow = A + (size_t)row * Nq;
        unsigned a0 = (Arow[lane] > 0.5f) ? 1u : 0u;
        unsigned a1 = (Arow[32 + lane] > 0.5f) ? 1u : 0u;
        unsigned m0 = __ballot_sync(0xffffffffu, a0);
        unsigned m1 = __ballot_sync(0xffffffffu, a1);
        unsigned lm = (lane == 0) ? 0u : (0xffffffffu >> (32 - lane));
        int n0 = __popc(m0);
        if (a0) { int p = __popc(m0 & lm); s_m[r * 64 + p] = lane;
                  if (by == 0) g_midx[row * Nq + p] = lane; }
        if (a1) { int p = n0 + __popc(m1 & lm); s_m[r * 64 + p] = 32 + lane;
                  if (by == 0) g_midx[row * Nq + p] = 32 + lane; }
        if (lane == 0) { int c = n0 + __popc(m1); s_cnt[r] = c;
                         if (by == 0) g_cnt[row] = c; }
    }

    if (by == 0 && t >= 128) {
        int r = (t - 128) >> 6, f = t & 63;
        int row = rp * 2 + r;
        float acc = b_embed[f];
#pragma unroll
        for (int k = 0; k < FINq; k++)
            acc += X[(size_t)row * FINq + k] * W_embed[k * Fq + f];
        g_H[(size_t)row * Fq + f] = fmaxf(acc, 0.0f);
    }
    __syncthreads();
    int cnt0 = s_cnt[0], ne = cnt0 + s_cnt[1];

    for (int i = t; i < ne * EDIMq; i += 256) {
        int kk = i >> 5, e = i & 31;
        int p  = (kk >= cnt0) ? 1 : 0;
        int kl = kk - (p ? cnt0 : 0);
        int row = rp * 2 + p;
        int m  = s_m[p * 64 + kl];
        float v = E[((size_t)row * Nq + m) * EDIMq + e];
        Es2[kk * EDIMq + e] = pack2(v, v);
    }
    __syncthreads();

    int c_a = c0 + t, c_b = c_a + 2048;
    unsigned long long w01[EDIMq];
#pragma unroll
    for (int e = 0; e < EDIMq; e++)
        w01[e] = pack2(W_edge[(size_t)e * FFq + c_a], W_edge[(size_t)e * FFq + c_b]);
    unsigned long long bias01 = pack2(b_edge[c_a], b_edge[c_b]);

    auto emit = [&](int kk, unsigned long long acc) {
        float a0, a1;
        unpack2(acc, a0, a1);
        int p  = (kk >= cnt0) ? 1 : 0;
        int kl = kk - (p ? cnt0 : 0);
        size_t slot = (size_t)(rp * 2 + p) * Nq + kl;
        g_Amat[slot * (FFq / 2) + c_a] =
            __floats2half2_rn(fmaxf(a0, 0.0f), fmaxf(a1, 0.0f));
    };

    int kk = 0;
    for (; kk + 2 <= ne; kk += 2) {
        unsigned long long acc0 = bias01, acc1 = bias01;
#pragma unroll
        for (int e = 0; e < EDIMq; e++) {
            acc0 = ffma2(Es2[kk * EDIMq + e],       w01[e], acc0);
            acc1 = ffma2(Es2[(kk + 1) * EDIMq + e], w01[e], acc1);
        }
        emit(kk, acc0);
        emit(kk + 1, acc1);
    }
    if (kk < ne) {
        unsigned long long acc0 = bias01;
#pragma unroll
        for (int e = 0; e < EDIMq; e++)
            acc0 = ffma2(Es2[kk * EDIMq + e], w01[e], acc0);
        emit(kk, acc0);
    }
}

// ---------------------------------------------------------------------------
// Kernel 2: one round, TMA-bulk double-buffered streaming. 256 blocks x 512.
// Chunk = 4 edges (32KB) moved by ONE cp.async.bulk (no LSU issue cost).
// Thread t consumes its uint4 per edge (ii = t>>4, j = (t&15)*4).
// ---------------------------------------------------------------------------
constexpr int RING_OFF = 0;                          // NRING*32768 = 65536
constexpr int HS_OFF   = NRING * CHUNK_E * 8192;     // 16384
constexpr int FLT_OFF  = HS_OFF + Nq * Fq * 4;       // 768 floats = 3072
constexpr int MB_OFF   = FLT_OFF + 768 * 4;          // 2 mbarriers
constexpr int KSM_TOTAL= MB_OFF + 64;                // 85056

__global__ __launch_bounds__(512) void k_round(
    const float* __restrict__ Hin, float* __restrict__ Hout,
    const float* __restrict__ gk, const float* __restrict__ grk,
    const float* __restrict__ gb, const float* __restrict__ grb)
{
    extern __shared__ __align__(16) char smem[];
    char*    ring = smem + RING_OFF;
    __half2* hs2  = reinterpret_cast<__half2*>(smem + HS_OFF);
    float*   fl   = reinterpret_cast<float*>(smem + FLT_OFF);
    float* xold = fl;            // 64
    float* aggv = fl + 64;       // 64
    float* h1   = fl + 128;      // 64
    float* xg1  = fl + 192;      // 192
    float* xg2  = fl + 384;      // 192
    float* hg2  = fl + 576;      // 192
    unsigned mb0 = smem_u32(smem + MB_OFF);           // full[0], full[1]

    int row = blockIdx.x;
    int b = row >> 6;
    int t = threadIdx.x;
    int q = t & 15;              // j-chunk: j = q*4..q*4+3

    int cnt = g_cnt[row];
    int nchunk = (cnt + CHUNK_E - 1) / CHUNK_E;
    const char* Asrc = reinterpret_cast<const char*>(g_Amat)
                     + (size_t)row * Nq * 8192;

    auto issue = [&](int c) {
        int s = c & 1;
        int e0 = c * CHUNK_E;
        unsigned bytes = (unsigned)(min(CHUNK_E, cnt - e0) * 8192);
        mbar_expect_tx(mb0 + s * 8, bytes);
        bulk_ld(smem_u32(ring + s * (CHUNK_E * 8192)), Asrc + (size_t)e0 * 8192,
                bytes, mb0 + s * 8);
    };

    // init barriers, fence, kick off both buffers (single thread)
    if (t == 0) {
        mbar_init(mb0, 1);
        mbar_init(mb0 + 8, 1);
        asm volatile("fence.proxy.async.shared::cta;" ::: "memory");
        if (nchunk > 0) issue(0);
        if (nchunk > 1) issue(1);
    }

    // stage source states (dup-half2) + xold while bulk copies fly
    __syncthreads();             // barrier init visible before any wait
    for (int idx = t; idx < cnt * Fq; idx += 512) {
        int e = idx >> 6, j = idx & 63;
        int m = g_midx[row * Nq + e];
        hs2[e * Fq + j] = __float2half2_rn(Hin[((size_t)b * Nq + m) * Fq + j]);
    }
    if (t >= 448) xold[t - 448] = Hin[(size_t)row * Fq + (t - 448)];
    __syncthreads();

    float flo = 0.0f, fhi = 0.0f;
    for (int c = 0; c < nchunk; c++) {
        int s = c & 1;
        mbar_wait(mb0 + s * 8, (c >> 1) & 1);
        int e0 = c * CHUNK_E;
        int nE = min(CHUNK_E, cnt - e0);
        const char* base = ring + s * (CHUNK_E * 8192);
#pragma unroll
        for (int el = 0; el < CHUNK_E; el++) {
            if (el < nE) {
                uint4 a  = *reinterpret_cast<const uint4*>(base + el * 8192 + t * 16);
                uint4 hv = *reinterpret_cast<const uint4*>(hs2 + (e0 + el) * Fq + q * 4);
                __half2 c2 = __hmul2(h2(a.x), h2(hv.x));
                c2 = __hfma2(h2(a.y), h2(hv.y), c2);
                c2 = __hfma2(h2(a.z), h2(hv.z), c2);
                c2 = __hfma2(h2(a.w), h2(hv.w), c2);
                float2 f = __half22float2(c2);
                flo += f.x;
                fhi += f.y;
            }
        }
        __syncthreads();         // slot s fully consumed
        if (t == 0 && c + NRING < nchunk) issue(c + NRING);
    }

    // reduce over the 16 j-lanes
    flo += __shfl_xor_sync(0xffffffffu, flo, 1);
    flo += __shfl_xor_sync(0xffffffffu, flo, 2);
    flo += __shfl_xor_sync(0xffffffffu, flo, 4);
    flo += __shfl_xor_sync(0xffffffffu, flo, 8);
    fhi += __shfl_xor_sync(0xffffffffu, fhi, 1);
    fhi += __shfl_xor_sync(0xffffffffu, fhi, 2);
    fhi += __shfl_xor_sync(0xffffffffu, fhi, 4);
    fhi += __shfl_xor_sync(0xffffffffu, fhi, 8);
    if (q == 0) {
        int ii = t >> 4;
        aggv[ii]      = flo;
        aggv[ii + 32] = fhi;
    }
    __syncthreads();

    // ---- GRU: one pass over gk computes both steps' input gates ----
    if (t < 192) {
        float a1 = gb[t], a2 = gb[t];
#pragma unroll 8
        for (int j = 0; j < Fq; j++) {
            float w = gk[j * 192 + t];
            a1 += xold[j] * w;
            a2 += aggv[j] * w;
        }
        xg1[t] = a1;
        xg2[t] = a2;
    }
    __syncthreads();
    if (t < Fq) {
        float z = sigm(xg1[t] + grb[t]);
        float rr = sigm(xg1[Fq + t] + grb[Fq + t]);
        float cand = tanhf(xg1[2 * Fq + t] + rr * grb[2 * Fq + t]);
        h1[t] = (1.0f - z) * cand;
    }
    __syncthreads();
    if (t < 192) {
        float hh = grb[t];
#pragma unroll 8
        for (int j = 0; j < Fq; j++) hh += h1[j] * grk[j * 192 + t];
        hg2[t] = hh;
    }
    __syncthreads();
    if (t < Fq) {
        float z = sigm(xg2[t] + hg2[t]);
        float rr = sigm(xg2[Fq + t] + hg2[Fq + t]);
        float cand = tanhf(xg2[2 * Fq + t] + rr * hg2[2 * Fq + t]);
        Hout[(size_t)row * Fq + t] = z * h1[t] + (1.0f - z) * cand;
    }
}

// ---------------------------------------------------------------------------
extern "C" void kernel_launch(void* const* d_in, const int* in_sizes, int n_in,
                              void* d_out, int out_size)
{
    const float* X       = (const float*)d_in[0];
    const float* A       = (const float*)d_in[1];
    const float* E       = (const float*)d_in[2];
    const float* W_embed = (const float*)d_in[3];
    const float* b_embed = (const float*)d_in[4];
    const float* W_edge  = (const float*)d_in[5];
    const float* b_edge  = (const float*)d_in[6];
    const float* gk      = (const float*)d_in[7];
    const float* grk     = (const float*)d_in[8];
    const float* gb      = (const float*)d_in[9];
    const float* grb     = (const float*)d_in[10];
    float* out = (float*)d_out;

    float *hbuf = nullptr, *h2buf = nullptr;
    cudaGetSymbolAddress((void**)&hbuf, g_H);
    cudaGetSymbolAddress((void**)&h2buf, g_H2);

    static bool attr_set = false;
    if (!attr_set) {
        cudaFuncSetAttribute(k_round, cudaFuncAttributeMaxDynamicSharedMemorySize,
                             KSM_TOTAL);
        attr_set = true;
    }

    k_edge<<<dim3(ROWS / 2, 8), 256>>>(A, E, X, W_embed, b_embed,
                                       W_edge, b_edge);
    k_round<<<ROWS, 512, KSM_TOTAL>>>(hbuf,  h2buf, gk, grk, gb, grb);
    k_round<<<ROWS, 512, KSM_TOTAL>>>(h2buf, hbuf,  gk, grk, gb, grb);
    k_round<<<ROWS, 512, KSM_TOTAL>>>(hbuf,  out,   gk, grk, gb, grb);
}